// round 4
// baseline (speedup 1.0000x reference)
#include <cuda_runtime.h>
#include <cuda_bf16.h>
#include <cstdint>
#include <cstddef>
#include <math.h>

#define Bsz 256
#define Dm  1024
#define Kg  7
#define VOCN 32000
#define SPAD 20   // u32 stride pad: 80B per row, 16B-aligned for ldmatrix, conflict-free

// ---------------- scratch (static device allocations only) ----------------
__device__ __nv_bfloat16 g_Wt_h[Kg * Dm * Dm];
__device__ __nv_bfloat16 g_Wt_l[Kg * Dm * Dm];
__device__ __nv_bfloat16 g_Ct_h[Kg * Dm * 2048];   // [g][e][k]: k<1024 = U^T, k>=1024 = V^T
__device__ __nv_bfloat16 g_Ct_l[Kg * Dm * 2048];
__device__ __nv_bfloat16 g_dec_h[VOCN * Dm];
__device__ __nv_bfloat16 g_dec_l[VOCN * Dm];
__device__ __nv_bfloat16 g_s1_h[Dm * 2048];
__device__ __nv_bfloat16 g_s1_l[Dm * 2048];
__device__ __nv_bfloat16 g_s2_h[Dm * Dm];
__device__ __nv_bfloat16 g_s2_l[Dm * Dm];
// activations (bf16 hi/lo)
__device__ __nv_bfloat16 g_hf_h[Bsz * 2048];       // [b][0:1024]=h, [1024:2048]=f_emb
__device__ __nv_bfloat16 g_hf_l[Bsz * 2048];
__device__ __nv_bfloat16 g_zh[2 * Bsz * Dm];       // DEQ ping-pong (perm space)
__device__ __nv_bfloat16 g_zl[2 * Bsz * Dm];
__device__ __nv_bfloat16 g_sth_h[Bsz * Dm];
__device__ __nv_bfloat16 g_sth_l[Bsz * Dm];
__device__ __nv_bfloat16 g_hn_h[Bsz * Dm];
__device__ __nv_bfloat16 g_hn_l[Bsz * Dm];
// fp32 scratch
__device__ float g_c[Bsz * Dm];                    // perm space
__device__ float g_gamma[Bsz];
__device__ int   g_ksel[Bsz];
__device__ int   g_perm[Bsz];
__device__ int   g_pos[Bsz];
__device__ int   g_gstart[Kg + 1];
__device__ float g_normsq[48];                     // index 1..40 used

// ---------------- small helpers ----------------
__device__ __forceinline__ float blockSum(float v) {
    __shared__ float rbuf[256];
    int t = threadIdx.x;
    rbuf[t] = v;
    __syncthreads();
    #pragma unroll
    for (int s = 128; s > 0; s >>= 1) {
        if (t < s) rbuf[t] += rbuf[t + s];
        __syncthreads();
    }
    float r = rbuf[0];
    __syncthreads();
    return r;
}

__device__ __forceinline__ void splitst(__nv_bfloat16* hb, __nv_bfloat16* lb, size_t i, float v) {
    __nv_bfloat16 hh = __float2bfloat16(v);
    hb[i] = hh;
    lb[i] = __float2bfloat16(v - __bfloat162float(hh));
}

__device__ __forceinline__ void ldm4(uint32_t* r, uint32_t addr) {
    asm volatile("ldmatrix.sync.aligned.m8n8.x4.shared.b16 {%0,%1,%2,%3}, [%4];"
                 : "=r"(r[0]), "=r"(r[1]), "=r"(r[2]), "=r"(r[3]) : "r"(addr));
}
__device__ __forceinline__ void ldm2(uint32_t& r0, uint32_t& r1, uint32_t addr) {
    asm volatile("ldmatrix.sync.aligned.m8n8.x2.shared.b16 {%0,%1}, [%2];"
                 : "=r"(r0), "=r"(r1) : "r"(addr));
}
__device__ __forceinline__ void mma_bf16(float* c, const uint32_t* a, uint32_t b0, uint32_t b1) {
    asm volatile("mma.sync.aligned.m16n8k16.row.col.f32.bf16.bf16.f32 "
                 "{%0,%1,%2,%3},{%4,%5,%6,%7},{%8,%9},{%0,%1,%2,%3};"
                 : "+f"(c[0]), "+f"(c[1]), "+f"(c[2]), "+f"(c[3])
                 : "r"(a[0]), "r"(a[1]), "r"(a[2]), "r"(a[3]), "r"(b0), "r"(b1));
}

// ---------------- conversion kernels ----------------
// DST: 0=dec, 1=s1, 2=s2
template<int DST>
__global__ void k_cvt(const float4* __restrict__ src, int n4)
{
    int i = blockIdx.x * 256 + threadIdx.x;
    if (i >= n4) return;
    __nv_bfloat16* dh = (DST == 0) ? g_dec_h : (DST == 1) ? g_s1_h : g_s2_h;
    __nv_bfloat16* dl = (DST == 0) ? g_dec_l : (DST == 1) ? g_s1_l : g_s2_l;
    float4 v = src[i];
    __nv_bfloat16 h0 = __float2bfloat16(v.x);
    __nv_bfloat16 h1 = __float2bfloat16(v.y);
    __nv_bfloat16 h2 = __float2bfloat16(v.z);
    __nv_bfloat16 h3 = __float2bfloat16(v.w);
    __nv_bfloat16 l0 = __float2bfloat16(v.x - __bfloat162float(h0));
    __nv_bfloat16 l1 = __float2bfloat16(v.y - __bfloat162float(h1));
    __nv_bfloat16 l2 = __float2bfloat16(v.z - __bfloat162float(h2));
    __nv_bfloat16 l3 = __float2bfloat16(v.w - __bfloat162float(h3));
    __nv_bfloat162* dh2 = (__nv_bfloat162*)(dh + (size_t)i * 4);
    __nv_bfloat162* dl2 = (__nv_bfloat162*)(dl + (size_t)i * 4);
    dh2[0] = __halves2bfloat162(h0, h1); dh2[1] = __halves2bfloat162(h2, h3);
    dl2[0] = __halves2bfloat162(l0, l1); dl2[1] = __halves2bfloat162(l2, l3);
}

// transpose+convert one [1024,1024] slice per z-group. WHICH: 0=W->Wt, 1=U->Ct(+0), 2=V->Ct(+1024)
template<int WHICH>
__global__ void k_cvtT(const float* __restrict__ src)
{
    __shared__ float t[32][33];
    int g = blockIdx.z;
    const float* s = src + (size_t)g * Dm * Dm;
    int ldd = (WHICH == 0) ? Dm : 2048;
    int ofs = (WHICH == 2) ? Dm : 0;
    __nv_bfloat16* dh = ((WHICH == 0) ? (__nv_bfloat16*)g_Wt_h : (__nv_bfloat16*)g_Ct_h) + (size_t)g * Dm * ldd;
    __nv_bfloat16* dl = ((WHICH == 0) ? (__nv_bfloat16*)g_Wt_l : (__nv_bfloat16*)g_Ct_l) + (size_t)g * Dm * ldd;

    int x = blockIdx.x * 32 + threadIdx.x;     // e (col of src)
    int y0 = blockIdx.y * 32;                  // k (row of src)
    #pragma unroll
    for (int i = threadIdx.y; i < 32; i += 8)
        t[i][threadIdx.x] = s[(size_t)(y0 + i) * Dm + x];
    __syncthreads();
    int x0 = blockIdx.x * 32;
    #pragma unroll
    for (int i = threadIdx.y; i < 32; i += 8) {
        float v = t[threadIdx.x][i];           // src[k=y0+tx][e=x0+i]
        size_t o = (size_t)(x0 + i) * ldd + ofs + y0 + threadIdx.x;
        __nv_bfloat16 hh = __float2bfloat16(v);
        dh[o] = hh;
        dl[o] = __float2bfloat16(v - __bfloat162float(hh));
    }
}

// ---------------- K0: routing / embeddings / gamma / pi + hf(bf16) ----------------
__global__ void k_setup(const float* __restrict__ h, const float* __restrict__ fs,
                        const float* __restrict__ fe, const int* __restrict__ tok,
                        const float* __restrict__ opemb, const float* __restrict__ numw,
                        const float* __restrict__ numb, const float* __restrict__ addr,
                        const float* __restrict__ fsw, const float* __restrict__ fsb,
                        const float* __restrict__ few, const float* __restrict__ feb,
                        const float* __restrict__ c1w, const float* __restrict__ c1b,
                        const float* __restrict__ c2w, const float* __restrict__ c2b,
                        float* __restrict__ out_pi)
{
    __shared__ float s_te[Dm];
    __shared__ float s_f[Dm];
    __shared__ float s_sc[Kg];
    int b = blockIdx.x, t = threadIdx.x;
    int tk = tok[b];
    float sv = fs[b], ev = fe[b];

    for (int j = t; j < Dm; j += 256) {
        float hv = h[(size_t)b * Dm + j];
        splitst(g_hf_h, g_hf_l, (size_t)b * 2048 + j, hv);
        float f = tanhf(fsw[j] * sv + fsb[j] + few[j] * ev + feb[j]);
        s_f[j] = f;
        splitst(g_hf_h, g_hf_l, (size_t)b * 2048 + Dm + j, f);
        float te;
        if (tk >= 7) te = ((float)tk - 7.0f) * numw[j] + numb[j];
        else         te = opemb[min(tk, 6) * Dm + j];
        s_te[j] = te;
    }
    __syncthreads();

    float p1 = 0.f, p2 = 0.f;
    for (int j = t; j < Dm; j += 256) {
        float a = s_te[j];
        float c = a + s_f[j];
        p1 += a * a;
        p2 += c * c;
    }
    float n1 = sqrtf(blockSum(p1));
    float n2 = sqrtf(blockSum(p2));
    float inv1 = 1.0f / fmaxf(n1, 1e-12f);
    float inv2 = 1.0f / fmaxf(n2, 1e-12f);

    for (int k = 0; k < Kg; k++) {
        float d1 = 0.f, d2 = 0.f, na = 0.f;
        for (int j = t; j < Dm; j += 256) {
            float a = addr[k * Dm + j];
            float te = s_te[j];
            d1 += te * a;
            d2 += (te + s_f[j]) * a;
            na += a * a;
        }
        d1 = blockSum(d1);
        d2 = blockSum(d2);
        na = blockSum(na);
        if (t == 0) {
            float invA = 1.0f / fmaxf(sqrtf(na), 1e-12f);
            s_sc[k] = (tk < 7) ? d1 * inv1 * invA : d2 * inv2 * invA;
        }
    }
    __syncthreads();

    if (t == 0) {
        float m = -1e30f;
        #pragma unroll
        for (int k = 0; k < Kg; k++) m = fmaxf(m, 5.0f * s_sc[k]);
        float ex[Kg], sum = 0.f;
        #pragma unroll
        for (int k = 0; k < Kg; k++) { ex[k] = expf(5.0f * s_sc[k] - m); sum += ex[k]; }
        float inv = 1.0f / sum;
        float ent = 0.f, best = -1.f;
        int am = 0;
        #pragma unroll
        for (int k = 0; k < Kg; k++) {
            float p = ex[k] * inv;
            out_pi[b * Kg + k] = p;
            ent -= p * logf(p + 1e-8f);
            if (p > best) { best = p; am = k; }
        }
        g_ksel[b] = am;
        float g = c2b[0];
        #pragma unroll
        for (int j = 0; j < 16; j++) {
            float hh = c1w[j * 2] * ent + c1b[j];
            hh = fmaxf(hh, 0.f);
            g += c2w[j] * hh;
        }
        g_gamma[b] = (g > 20.f) ? g : log1pf(expf(g));
    }
}

// ---------------- K0b: grouping + per-run state reset ----------------
__global__ void k_group()
{
    __shared__ int sk[Bsz];
    __shared__ int cnt[Kg];
    __shared__ int cur[Kg];
    int t = threadIdx.x;
    sk[t] = g_ksel[t];
    __syncthreads();
    if (t < Kg) {
        int c = 0;
        for (int b = 0; b < Bsz; b++) c += (sk[b] == t);
        cnt[t] = c;
    }
    __syncthreads();
    if (t == 0) {
        int s = 0;
        for (int k = 0; k < Kg; k++) { cur[k] = s; g_gstart[k] = s; s += cnt[k]; }
        g_gstart[Kg] = s;
    }
    __syncthreads();
    int myk = sk[t];
    int rank = 0;
    for (int b = 0; b < t; b++) rank += (sk[b] == myk);
    int p = cur[myk] + rank;
    g_perm[p] = t;
    g_pos[t] = p;
    if (t < 48) g_normsq[t] = 0.f;
}

// ---------------- unified NT tensor-core GEMM: C = A[M,K] @ B[N,K]^T ----------------
// bf16x3 split: acc = Ah*Bh + Ah*Bl + Al*Bh, fp32 accumulate.
// ASRC: 0=g_hf(K=2048), 1=g_hf gathered (c-prep), 2=z ping-pong, 3=g_stabh, 4=g_hn
// BSRC: 0=Wt(+g), 1=Ct(+g), 2=s1, 3=s2, 4=dec
// EPI : 0=logits, 1=stab1, 2=stab2, 3=cprep, 4=deq
template<int MFRAG, int WARPS_M, int WARPS_N, int ASRC, int BSRC, int EPI,
         bool ZEROA, bool DONECHK, bool GROUPED>
__global__ void __launch_bounds__(WARPS_M * WARPS_N * 32)
k_mma(const float* __restrict__ bias, float* __restrict__ OutF,
      const float* __restrict__ Hin, int iter, int Ndim, int Kdim)
{
    constexpr int BM = MFRAG * WARPS_M * 16;
    constexpr int BN = WARPS_N * 32;
    constexpr int NT = WARPS_M * WARPS_N * 32;

    if (DONECHK) {
        #pragma unroll 1
        for (int j = 1; j < iter; j++)
            if (g_normsq[j] < 1e-8f) return;
    }
    int gs = 0, Mg = Bsz, gidx = 0;
    if (GROUPED) {
        gidx = blockIdx.z;
        gs = g_gstart[gidx];
        Mg = g_gstart[gidx + 1] - gs;
        if ((int)blockIdx.y * BM >= Mg) return;
    }
    const int m0 = blockIdx.y * BM;
    const int n0 = blockIdx.x * BN;
    const int tid = threadIdx.x;
    const int lane = tid & 31, w = tid >> 5;
    const int wm = w % WARPS_M, wn = w / WARPS_M;
    const int rb = (iter - 1) & 1;

    // A / B pointers as u32 (2 bf16 each, K-contiguous)
    const uint32_t* Ah32;
    const uint32_t* Al32;
    if (ASRC == 0 || ASRC == 1) { Ah32 = (const uint32_t*)g_hf_h; Al32 = (const uint32_t*)g_hf_l; }
    else if (ASRC == 2) {
        Ah32 = (const uint32_t*)(g_zh + (size_t)rb * Bsz * Dm);
        Al32 = (const uint32_t*)(g_zl + (size_t)rb * Bsz * Dm);
    } else if (ASRC == 3) { Ah32 = (const uint32_t*)g_sth_h; Al32 = (const uint32_t*)g_sth_l; }
    else                  { Ah32 = (const uint32_t*)g_hn_h;  Al32 = (const uint32_t*)g_hn_l; }

    const uint32_t* Bh32;
    const uint32_t* Bl32;
    if (BSRC == 0) {
        Bh32 = (const uint32_t*)(g_Wt_h + (size_t)gidx * Dm * Dm);
        Bl32 = (const uint32_t*)(g_Wt_l + (size_t)gidx * Dm * Dm);
    } else if (BSRC == 1) {
        Bh32 = (const uint32_t*)(g_Ct_h + (size_t)gidx * Dm * 2048);
        Bl32 = (const uint32_t*)(g_Ct_l + (size_t)gidx * Dm * 2048);
    } else if (BSRC == 2) { Bh32 = (const uint32_t*)g_s1_h; Bl32 = (const uint32_t*)g_s1_l; }
    else if (BSRC == 3)   { Bh32 = (const uint32_t*)g_s2_h; Bl32 = (const uint32_t*)g_s2_l; }
    else                  { Bh32 = (const uint32_t*)g_dec_h; Bl32 = (const uint32_t*)g_dec_l; }

    const int ldk = Kdim >> 1;    // u32 stride per row

    __shared__ uint32_t sA[2 * BM * SPAD];
    __shared__ uint32_t sB[2 * BN * SPAD];
    const uint32_t sA_addr = (uint32_t)__cvta_generic_to_shared(sA);
    const uint32_t sB_addr = (uint32_t)__cvta_generic_to_shared(sB);

    float acc[MFRAG][4][4];
    #pragma unroll
    for (int a = 0; a < MFRAG; a++)
        #pragma unroll
        for (int b = 0; b < 4; b++)
            #pragma unroll
            for (int c = 0; c < 4; c++) acc[a][b][c] = 0.f;

    if (!ZEROA) {
        const int ksteps = Kdim >> 5;  // 32 elems (16 u32) per step
        #pragma unroll 1
        for (int kt = 0; kt < ksteps; kt++) {
            constexpr int AIT = BM * 16 / NT;
            #pragma unroll
            for (int it = 0; it < AIT; it++) {
                int i = tid + it * NT;
                int r = i >> 4, c = i & 15;
                uint32_t vh = 0, vl = 0;
                int rloc = m0 + r;
                bool ok = (!GROUPED) || (rloc < Mg);
                if (ok) {
                    int grow;
                    if (GROUPED) grow = (ASRC == 1) ? g_perm[gs + rloc] : (gs + rloc);
                    else         grow = rloc;
                    size_t off = (size_t)grow * ldk + (size_t)kt * 16 + c;
                    vh = Ah32[off];
                    vl = Al32[off];
                }
                sA[r * SPAD + c] = vh;
                sA[BM * SPAD + r * SPAD + c] = vl;
            }
            constexpr int BIT = BN * 16 / NT;
            #pragma unroll
            for (int it = 0; it < BIT; it++) {
                int i = tid + it * NT;
                int r = i >> 4, c = i & 15;
                size_t off = (size_t)(n0 + r) * ldk + (size_t)kt * 16 + c;
                sB[r * SPAD + c] = Bh32[off];
                sB[BN * SPAD + r * SPAD + c] = Bl32[off];
            }
            __syncthreads();
            #pragma unroll
            for (int ch = 0; ch < 2; ch++) {
                uint32_t ah[MFRAG][4], al[MFRAG][4];
                #pragma unroll
                for (int mf = 0; mf < MFRAG; mf++) {
                    int arow = (wm * MFRAG + mf) * 16 + (lane & 7) + ((lane >> 3) & 1) * 8;
                    int acol = ch * 8 + (lane >> 4) * 4;
                    uint32_t ad = sA_addr + (uint32_t)((arow * SPAD + acol) * 4);
                    ldm4(ah[mf], ad);
                    ldm4(al[mf], ad + (uint32_t)(BM * SPAD * 4));
                }
                #pragma unroll
                for (int ns = 0; ns < 4; ns++) {
                    int l16 = lane & 15;
                    int brow = wn * 32 + ns * 8 + (l16 & 7);
                    int bcol = ch * 8 + ((l16 >> 3) & 1) * 4;
                    uint32_t bd = sB_addr + (uint32_t)((brow * SPAD + bcol) * 4);
                    uint32_t bh0, bh1, bl0, bl1;
                    ldm2(bh0, bh1, bd);
                    ldm2(bl0, bl1, bd + (uint32_t)(BN * SPAD * 4));
                    #pragma unroll
                    for (int mf = 0; mf < MFRAG; mf++) {
                        mma_bf16(acc[mf][ns], ah[mf], bh0, bh1);
                        mma_bf16(acc[mf][ns], ah[mf], bl0, bl1);
                        mma_bf16(acc[mf][ns], al[mf], bh0, bh1);
                    }
                }
            }
            __syncthreads();
        }
    }

    // ---- epilogue ----
    int f40wb = 0;
    if (EPI == 2) {
        int f = 40;
        #pragma unroll 1
        for (int j = 1; j <= 40; j++)
            if (g_normsq[j] < 1e-8f) { f = j; break; }
        f40wb = f & 1;
    }
    float nsum = 0.f;
    const int rowb = m0 + wm * MFRAG * 16 + (lane >> 2);
    const int colb = n0 + wn * 32 + 2 * (lane & 3);
    #pragma unroll
    for (int mf = 0; mf < MFRAG; mf++) {
        #pragma unroll
        for (int ns = 0; ns < 4; ns++) {
            #pragma unroll
            for (int k = 0; k < 4; k++) {
                int r = rowb + mf * 16 + ((k >> 1) ? 8 : 0);
                int n = colb + ns * 8 + (k & 1);
                if (GROUPED && r >= Mg) continue;
                float val = acc[mf][ns][k];
                if (EPI == 0) {
                    OutF[(size_t)r * Ndim + n] = val + bias[n];
                } else if (EPI == 1) {
                    float v = tanhf(val + bias[n]);
                    splitst(g_sth_h, g_sth_l, (size_t)r * Dm + n, v);
                } else if (EPI == 2) {
                    float sg = 1.f / (1.f + expf(-(val + bias[n])));
                    size_t zi = (size_t)(f40wb * Bsz + g_pos[r]) * Dm + n;
                    float z = __bfloat162float(g_zh[zi]) + __bfloat162float(g_zl[zi]);
                    float hn = Hin[(size_t)r * Dm + n] + g_gamma[r] * sg * z;
                    OutF[(size_t)r * Dm + n] = hn;
                    splitst(g_hn_h, g_hn_l, (size_t)r * Dm + n, hn);
                } else if (EPI == 3) {
                    g_c[(size_t)(gs + r) * Dm + n] = val;
                } else {   // EPI == 4: DEQ step
                    size_t gi = (size_t)(gs + r) * Dm + n;
                    float v = tanhf(val + g_c[gi]);
                    float zp = 0.f;
                    if (!ZEROA) {
                        size_t zi = (size_t)rb * Bsz * Dm + gi;
                        zp = __bfloat162float(g_zh[zi]) + __bfloat162float(g_zl[zi]);
                    }
                    float d = v - zp;
                    nsum += d * d;
                    size_t zo = (size_t)(iter & 1) * Bsz * Dm + gi;
                    __nv_bfloat16 hh = __float2bfloat16(v);
                    g_zh[zo] = hh;
                    g_zl[zo] = __float2bfloat16(v - __bfloat162float(hh));
                }
            }
        }
    }
    if (EPI == 4) {
        float tot = blockSum(nsum);
        if (tid == 0) atomicAdd(&g_normsq[iter], tot);
    }
}

// ---------------- host ----------------
extern "C" void kernel_launch(void* const* d_in, const int* in_sizes, int n_in,
                              void* d_out, int out_size)
{
    const float* h      = (const float*)d_in[0];
    const float* fs     = (const float*)d_in[1];
    const float* fe     = (const float*)d_in[2];
    const int*   tok    = (const int*)  d_in[3];
    const float* opemb  = (const float*)d_in[4];
    const float* numw   = (const float*)d_in[5];
    const float* numb   = (const float*)d_in[6];
    const float* addr   = (const float*)d_in[7];
    const float* W      = (const float*)d_in[8];
    const float* U      = (const float*)d_in[9];
    const float* V      = (const float*)d_in[10];
    const float* fsw    = (const float*)d_in[11];
    const float* fsb    = (const float*)d_in[12];
    const float* few    = (const float*)d_in[13];
    const float* feb    = (const float*)d_in[14];
    const float* s1w    = (const float*)d_in[15];
    const float* s1b    = (const float*)d_in[16];
    const float* s2w    = (const float*)d_in[17];
    const float* s2b    = (const float*)d_in[18];
    const float* c1w    = (const float*)d_in[19];
    const float* c1b    = (const float*)d_in[20];
    const float* c2w    = (const float*)d_in[21];
    const float* c2b    = (const float*)d_in[22];
    const float* decw   = (const float*)d_in[23];
    const float* decb   = (const float*)d_in[24];

    float* out        = (float*)d_out;
    float* out_h      = out;
    float* out_logits = out + (size_t)Bsz * Dm;
    float* out_pi     = out + (size_t)Bsz * Dm + (size_t)Bsz * VOCN;

    // ---- weight conversion ----
    k_cvt<0><<<(VOCN * Dm / 4 + 255) / 256, 256>>>((const float4*)decw, VOCN * Dm / 4);
    k_cvt<1><<<(Dm * 2048 / 4 + 255) / 256, 256>>>((const float4*)s1w, Dm * 2048 / 4);
    k_cvt<2><<<(Dm * Dm / 4 + 255) / 256, 256>>>((const float4*)s2w, Dm * Dm / 4);
    dim3 tg(32, 32, Kg), tb(32, 8);
    k_cvtT<0><<<tg, tb>>>(W);
    k_cvtT<1><<<tg, tb>>>(U);
    k_cvtT<2><<<tg, tb>>>(V);

    // ---- routing / embeddings ----
    k_setup<<<Bsz, 256>>>(h, fs, fe, tok, opemb, numw, numb, addr,
                          fsw, fsb, few, feb, c1w, c1b, c2w, c2b, out_pi);
    k_group<<<1, 256>>>();

    // ---- c = [h, f_emb] @ [U;V]^T  (grouped, gathered, K=2048) ----
    k_mma<1, 2, 4, 1, 1, 3, false, false, true>
        <<<dim3(8, 8, Kg), 256>>>(nullptr, nullptr, nullptr, 0, Dm, 2048);

    // ---- DEQ fixed point: iter 1 (z=tanh(c)), iters 2..40 ping-pong ----
    k_mma<1, 2, 4, 2, 0, 4, true, false, true>
        <<<dim3(8, 8, Kg), 256>>>(nullptr, nullptr, nullptr, 1, Dm, Dm);
    for (int i = 2; i <= 40; i++) {
        k_mma<1, 2, 4, 2, 0, 4, false, true, true>
            <<<dim3(8, 8, Kg), 256>>>(nullptr, nullptr, nullptr, i, Dm, Dm);
    }

    // ---- stab_h = tanh([h,f] @ s1^T + b1) ----
    k_mma<1, 2, 4, 0, 2, 1, false, false, false>
        <<<dim3(8, 8), 256>>>(s1b, nullptr, nullptr, 0, Dm, 2048);
    // ---- h_next = h + gamma * sigmoid(stab_h @ s2^T + b2) * z_star ----
    k_mma<1, 2, 4, 3, 3, 2, false, false, false>
        <<<dim3(8, 8), 256>>>(s2b, out_h, h, 0, Dm, Dm);
    // ---- logits = h_next @ dec^T + decb ----
    k_mma<2, 4, 2, 4, 4, 0, false, false, false>
        <<<dim3(VOCN / 64, Bsz / 128), 256>>>(decb, out_logits, nullptr, 0, VOCN, Dm);
}

// round 5
// speedup vs baseline: 2.1756x; 2.1756x over previous
#include <cuda_runtime.h>
#include <cuda_bf16.h>
#include <cstdint>
#include <cstddef>
#include <math.h>

#define Bsz 256
#define Dm  1024
#define Kg  7
#define VOCN 32000
#define SPAD 20   // u32 row stride: 80B, 16B-aligned (ldmatrix + cp.async), conflict-free

// ---------------- scratch (static device allocations only) ----------------
__device__ __align__(256) __nv_bfloat16 g_Wt_h[Kg * Dm * Dm];
__device__ __align__(256) __nv_bfloat16 g_Wt_l[Kg * Dm * Dm];
__device__ __align__(256) __nv_bfloat16 g_Ct_h[Kg * Dm * 2048];  // [g][e][k]: k<1024=U^T, k>=1024=V^T
__device__ __align__(256) __nv_bfloat16 g_Ct_l[Kg * Dm * 2048];
__device__ __align__(256) __nv_bfloat16 g_dec_h[VOCN * Dm];
__device__ __align__(256) __nv_bfloat16 g_dec_l[VOCN * Dm];
__device__ __align__(256) __nv_bfloat16 g_s1_h[Dm * 2048];
__device__ __align__(256) __nv_bfloat16 g_s1_l[Dm * 2048];
__device__ __align__(256) __nv_bfloat16 g_s2_h[Dm * Dm];
__device__ __align__(256) __nv_bfloat16 g_s2_l[Dm * Dm];
// activations (bf16 hi/lo)
__device__ __align__(256) __nv_bfloat16 g_hf_h[Bsz * 2048];   // [b][0:1024]=h, [1024:2048]=f_emb
__device__ __align__(256) __nv_bfloat16 g_hf_l[Bsz * 2048];
__device__ __align__(256) __nv_bfloat16 g_zh[2 * Bsz * Dm];   // DEQ ping-pong pair (perm space)
__device__ __align__(256) __nv_bfloat16 g_zl[2 * Bsz * Dm];
__device__ __align__(256) __nv_bfloat16 g_sth_h[Bsz * Dm];
__device__ __align__(256) __nv_bfloat16 g_sth_l[Bsz * Dm];
__device__ __align__(256) __nv_bfloat16 g_hn_h[Bsz * Dm];
__device__ __align__(256) __nv_bfloat16 g_hn_l[Bsz * Dm];
// fp32 scratch
__device__ float g_zf32[Bsz * Dm];                 // fp32 z iterate (perm space)
__device__ float g_c[Bsz * Dm];                    // perm space
__device__ float g_gamma[Bsz];
__device__ int   g_ksel[Bsz];
__device__ int   g_perm[Bsz];
__device__ int   g_pos[Bsz];
__device__ int   g_gstart[Kg + 1];
__device__ float g_normsq[48];
__device__ int   g_done;
__device__ int   g_cnt;

// ---------------- small helpers ----------------
__device__ __forceinline__ float blockSum256(float v) {
    __shared__ float rbuf[256];
    int t = threadIdx.x;
    rbuf[t] = v;
    __syncthreads();
    #pragma unroll
    for (int s = 128; s > 0; s >>= 1) {
        if (t < s) rbuf[t] += rbuf[t + s];
        __syncthreads();
    }
    float r = rbuf[0];
    __syncthreads();
    return r;
}

__device__ __forceinline__ void splitst(__nv_bfloat16* hb, __nv_bfloat16* lb, size_t i, float v) {
    __nv_bfloat16 hh = __float2bfloat16(v);
    hb[i] = hh;
    lb[i] = __float2bfloat16(v - __bfloat162float(hh));
}

__device__ __forceinline__ void ldm4(uint32_t* r, uint32_t addr) {
    asm volatile("ldmatrix.sync.aligned.m8n8.x4.shared.b16 {%0,%1,%2,%3}, [%4];"
                 : "=r"(r[0]), "=r"(r[1]), "=r"(r[2]), "=r"(r[3]) : "r"(addr));
}
__device__ __forceinline__ void ldm2(uint32_t& r0, uint32_t& r1, uint32_t addr) {
    asm volatile("ldmatrix.sync.aligned.m8n8.x2.shared.b16 {%0,%1}, [%2];"
                 : "=r"(r0), "=r"(r1) : "r"(addr));
}
__device__ __forceinline__ void mma_bf16(float* c, const uint32_t* a, uint32_t b0, uint32_t b1) {
    asm volatile("mma.sync.aligned.m16n8k16.row.col.f32.bf16.bf16.f32 "
                 "{%0,%1,%2,%3},{%4,%5,%6,%7},{%8,%9},{%0,%1,%2,%3};"
                 : "+f"(c[0]), "+f"(c[1]), "+f"(c[2]), "+f"(c[3])
                 : "r"(a[0]), "r"(a[1]), "r"(a[2]), "r"(a[3]), "r"(b0), "r"(b1));
}
__device__ __forceinline__ void cpa16(uint32_t dst, const void* src, bool ok) {
    int sz = ok ? 16 : 0;
    asm volatile("cp.async.cg.shared.global [%0], [%1], 16, %2;"
                 :: "r"(dst), "l"(src), "r"(sz));
}

// ---------------- conversion kernels ----------------
template<int DST>
__global__ void k_cvt(const float4* __restrict__ src, int n4)
{
    int i = blockIdx.x * 256 + threadIdx.x;
    if (i >= n4) return;
    __nv_bfloat16* dh = (DST == 0) ? g_dec_h : (DST == 1) ? g_s1_h : g_s2_h;
    __nv_bfloat16* dl = (DST == 0) ? g_dec_l : (DST == 1) ? g_s1_l : g_s2_l;
    float4 v = src[i];
    __nv_bfloat16 h0 = __float2bfloat16(v.x);
    __nv_bfloat16 h1 = __float2bfloat16(v.y);
    __nv_bfloat16 h2 = __float2bfloat16(v.z);
    __nv_bfloat16 h3 = __float2bfloat16(v.w);
    __nv_bfloat16 l0 = __float2bfloat16(v.x - __bfloat162float(h0));
    __nv_bfloat16 l1 = __float2bfloat16(v.y - __bfloat162float(h1));
    __nv_bfloat16 l2 = __float2bfloat16(v.z - __bfloat162float(h2));
    __nv_bfloat16 l3 = __float2bfloat16(v.w - __bfloat162float(h3));
    __nv_bfloat162* dh2 = (__nv_bfloat162*)(dh + (size_t)i * 4);
    __nv_bfloat162* dl2 = (__nv_bfloat162*)(dl + (size_t)i * 4);
    dh2[0] = __halves2bfloat162(h0, h1); dh2[1] = __halves2bfloat162(h2, h3);
    dl2[0] = __halves2bfloat162(l0, l1); dl2[1] = __halves2bfloat162(l2, l3);
}

// transpose+convert one [1024,1024] slice per z. WHICH: 0=W->Wt, 1=U->Ct(+0), 2=V->Ct(+1024)
template<int WHICH>
__global__ void k_cvtT(const float* __restrict__ src)
{
    __shared__ float t[32][33];
    int g = blockIdx.z;
    const float* s = src + (size_t)g * Dm * Dm;
    int ldd = (WHICH == 0) ? Dm : 2048;
    int ofs = (WHICH == 2) ? Dm : 0;
    __nv_bfloat16* dh = ((WHICH == 0) ? (__nv_bfloat16*)g_Wt_h : (__nv_bfloat16*)g_Ct_h) + (size_t)g * Dm * ldd;
    __nv_bfloat16* dl = ((WHICH == 0) ? (__nv_bfloat16*)g_Wt_l : (__nv_bfloat16*)g_Ct_l) + (size_t)g * Dm * ldd;

    int x = blockIdx.x * 32 + threadIdx.x;
    int y0 = blockIdx.y * 32;
    #pragma unroll
    for (int i = threadIdx.y; i < 32; i += 8)
        t[i][threadIdx.x] = s[(size_t)(y0 + i) * Dm + x];
    __syncthreads();
    int x0 = blockIdx.x * 32;
    #pragma unroll
    for (int i = threadIdx.y; i < 32; i += 8) {
        float v = t[threadIdx.x][i];
        size_t o = (size_t)(x0 + i) * ldd + ofs + y0 + threadIdx.x;
        __nv_bfloat16 hh = __float2bfloat16(v);
        dh[o] = hh;
        dl[o] = __float2bfloat16(v - __bfloat162float(hh));
    }
}

// ---------------- K0: routing / embeddings / gamma / pi + hf(bf16) ----------------
__global__ void k_setup(const float* __restrict__ h, const float* __restrict__ fs,
                        const float* __restrict__ fe, const int* __restrict__ tok,
                        const float* __restrict__ opemb, const float* __restrict__ numw,
                        const float* __restrict__ numb, const float* __restrict__ addr,
                        const float* __restrict__ fsw, const float* __restrict__ fsb,
                        const float* __restrict__ few, const float* __restrict__ feb,
                        const float* __restrict__ c1w, const float* __restrict__ c1b,
                        const float* __restrict__ c2w, const float* __restrict__ c2b,
                        float* __restrict__ out_pi)
{
    __shared__ float s_te[Dm];
    __shared__ float s_f[Dm];
    __shared__ float s_sc[Kg];
    int b = blockIdx.x, t = threadIdx.x;
    int tk = tok[b];
    float sv = fs[b], ev = fe[b];

    for (int j = t; j < Dm; j += 256) {
        float hv = h[(size_t)b * Dm + j];
        splitst(g_hf_h, g_hf_l, (size_t)b * 2048 + j, hv);
        float f = tanhf(fsw[j] * sv + fsb[j] + few[j] * ev + feb[j]);
        s_f[j] = f;
        splitst(g_hf_h, g_hf_l, (size_t)b * 2048 + Dm + j, f);
        float te;
        if (tk >= 7) te = ((float)tk - 7.0f) * numw[j] + numb[j];
        else         te = opemb[min(tk, 6) * Dm + j];
        s_te[j] = te;
    }
    __syncthreads();

    float p1 = 0.f, p2 = 0.f;
    for (int j = t; j < Dm; j += 256) {
        float a = s_te[j];
        float c = a + s_f[j];
        p1 += a * a;
        p2 += c * c;
    }
    float n1 = sqrtf(blockSum256(p1));
    float n2 = sqrtf(blockSum256(p2));
    float inv1 = 1.0f / fmaxf(n1, 1e-12f);
    float inv2 = 1.0f / fmaxf(n2, 1e-12f);

    for (int k = 0; k < Kg; k++) {
        float d1 = 0.f, d2 = 0.f, na = 0.f;
        for (int j = t; j < Dm; j += 256) {
            float a = addr[k * Dm + j];
            float te = s_te[j];
            d1 += te * a;
            d2 += (te + s_f[j]) * a;
            na += a * a;
        }
        d1 = blockSum256(d1);
        d2 = blockSum256(d2);
        na = blockSum256(na);
        if (t == 0) {
            float invA = 1.0f / fmaxf(sqrtf(na), 1e-12f);
            s_sc[k] = (tk < 7) ? d1 * inv1 * invA : d2 * inv2 * invA;
        }
    }
    __syncthreads();

    if (t == 0) {
        float m = -1e30f;
        #pragma unroll
        for (int k = 0; k < Kg; k++) m = fmaxf(m, 5.0f * s_sc[k]);
        float ex[Kg], sum = 0.f;
        #pragma unroll
        for (int k = 0; k < Kg; k++) { ex[k] = expf(5.0f * s_sc[k] - m); sum += ex[k]; }
        float inv = 1.0f / sum;
        float ent = 0.f, best = -1.f;
        int am = 0;
        #pragma unroll
        for (int k = 0; k < Kg; k++) {
            float p = ex[k] * inv;
            out_pi[b * Kg + k] = p;
            ent -= p * logf(p + 1e-8f);
            if (p > best) { best = p; am = k; }
        }
        g_ksel[b] = am;
        float g = c2b[0];
        #pragma unroll
        for (int j = 0; j < 16; j++) {
            float hh = c1w[j * 2] * ent + c1b[j];
            hh = fmaxf(hh, 0.f);
            g += c2w[j] * hh;
        }
        g_gamma[b] = (g > 20.f) ? g : log1pf(expf(g));
    }
}

// ---------------- K0b: grouping + per-run state reset ----------------
__global__ void k_group()
{
    __shared__ int sk[Bsz];
    __shared__ int cnt[Kg];
    __shared__ int cur[Kg];
    int t = threadIdx.x;
    sk[t] = g_ksel[t];
    __syncthreads();
    if (t < Kg) {
        int c = 0;
        for (int b = 0; b < Bsz; b++) c += (sk[b] == t);
        cnt[t] = c;
    }
    __syncthreads();
    if (t == 0) {
        int s = 0;
        for (int k = 0; k < Kg; k++) { cur[k] = s; g_gstart[k] = s; s += cnt[k]; }
        g_gstart[Kg] = s;
        g_done = 0;
        g_cnt = 0;
    }
    __syncthreads();
    int myk = sk[t];
    int rank = 0;
    for (int b = 0; b < t; b++) rank += (sk[b] == myk);
    int p = cur[myk] + rank;
    g_perm[p] = t;
    g_pos[t] = p;
    if (t < 48) g_normsq[t] = 0.f;
}

// ---------------- unified pipelined NT tensor-core GEMM: C = A[M,K] @ B[N,K]^T ----------------
// bf16x3 split: acc = Ah*Bh + Ah*Bl + Al*Bh, fp32 accumulate. cp.async 2-stage pipeline.
// ASRC: 0=g_hf(K=2048), 1=g_hf gathered (c-prep), 2=z ping-pong, 3=g_stabh, 4=g_hn
// BSRC: 0=Wt(+g), 1=Ct(+g), 2=s1, 3=s2, 4=dec
// EPI : 0=logits, 1=stab1, 2=stab2, 3=cprep, 4=deq
template<int MFRAG, int WARPS_M, int WARPS_N, int ASRC, int BSRC, int EPI,
         bool ZEROA, bool DONECHK, bool GROUPED>
__global__ void __launch_bounds__(WARPS_M * WARPS_N * 32)
k_mma(const float* __restrict__ bias, float* __restrict__ OutF,
      const float* __restrict__ Hin, int iter, int Ndim, int Kdim)
{
    constexpr int BM = MFRAG * WARPS_M * 16;
    constexpr int BN = WARPS_N * 32;
    constexpr int NT = WARPS_M * WARPS_N * 32;
    constexpr int ASZ = 2 * BM * SPAD;   // hi+lo, one stage (u32)
    constexpr int BSZ = 2 * BN * SPAD;

    if (DONECHK) { if (g_done) return; }

    int gs = 0, Mg = Bsz, gidx = 0;
    if (GROUPED) {
        gidx = blockIdx.z;
        gs = g_gstart[gidx];
        Mg = g_gstart[gidx + 1] - gs;
    }
    const int m0 = blockIdx.y * BM;
    const int n0 = blockIdx.x * BN;
    const int tid = threadIdx.x;
    const int lane = tid & 31, w = tid >> 5;
    const int wm = w % WARPS_M, wn = w / WARPS_M;
    const int rb = (iter - 1) & 1;
    const bool haswork = (!GROUPED) || (m0 < Mg);

    __shared__ uint32_t sA[2 * ASZ];
    __shared__ uint32_t sB[2 * BSZ];

    float acc[MFRAG][4][4];
    #pragma unroll
    for (int a = 0; a < MFRAG; a++)
        #pragma unroll
        for (int b = 0; b < 4; b++)
            #pragma unroll
            for (int c = 0; c < 4; c++) acc[a][b][c] = 0.f;
    float nsum = 0.f;

    if (haswork) {
        const uint32_t* Ah32;
        const uint32_t* Al32;
        if (ASRC == 0 || ASRC == 1) { Ah32 = (const uint32_t*)g_hf_h; Al32 = (const uint32_t*)g_hf_l; }
        else if (ASRC == 2) {
            Ah32 = (const uint32_t*)(g_zh + (size_t)rb * Bsz * Dm);
            Al32 = (const uint32_t*)(g_zl + (size_t)rb * Bsz * Dm);
        } else if (ASRC == 3) { Ah32 = (const uint32_t*)g_sth_h; Al32 = (const uint32_t*)g_sth_l; }
        else                  { Ah32 = (const uint32_t*)g_hn_h;  Al32 = (const uint32_t*)g_hn_l; }

        const uint32_t* Bh32;
        const uint32_t* Bl32;
        if (BSRC == 0) {
            Bh32 = (const uint32_t*)(g_Wt_h + (size_t)gidx * Dm * Dm);
            Bl32 = (const uint32_t*)(g_Wt_l + (size_t)gidx * Dm * Dm);
        } else if (BSRC == 1) {
            Bh32 = (const uint32_t*)(g_Ct_h + (size_t)gidx * Dm * 2048);
            Bl32 = (const uint32_t*)(g_Ct_l + (size_t)gidx * Dm * 2048);
        } else if (BSRC == 2) { Bh32 = (const uint32_t*)g_s1_h; Bl32 = (const uint32_t*)g_s1_l; }
        else if (BSRC == 3)   { Bh32 = (const uint32_t*)g_s2_h; Bl32 = (const uint32_t*)g_s2_l; }
        else                  { Bh32 = (const uint32_t*)g_dec_h; Bl32 = (const uint32_t*)g_dec_l; }

        const int ldk = Kdim >> 1;
        const uint32_t sAa = (uint32_t)__cvta_generic_to_shared(sA);
        const uint32_t sBa = (uint32_t)__cvta_generic_to_shared(sB);

        if (!ZEROA) {
            const int ksteps = Kdim >> 5;

            auto stage_load = [&](int kt, int s) {
                #pragma unroll
                for (int it = 0; it < (BM * 8) / NT; it++) {
                    int idx = tid + it * NT;
                    int row = idx >> 3, half = (idx >> 2) & 1, c4 = (idx & 3) * 4;
                    int rloc = m0 + row;
                    bool ok = (!GROUPED) || (rloc < Mg);
                    int grow = rloc;
                    if (GROUPED) {
                        int rr = ok ? (gs + rloc) : gs;
                        grow = (ASRC == 1) ? g_perm[rr] : rr;
                    }
                    const uint32_t* src = (half ? Al32 : Ah32) + (size_t)grow * ldk + kt * 16 + c4;
                    cpa16(sAa + (uint32_t)((s * ASZ + half * BM * SPAD + row * SPAD + c4) * 4), src, ok);
                }
                #pragma unroll
                for (int it = 0; it < (BN * 8) / NT; it++) {
                    int idx = tid + it * NT;
                    int row = idx >> 3, half = (idx >> 2) & 1, c4 = (idx & 3) * 4;
                    const uint32_t* src = (half ? Bl32 : Bh32) + (size_t)(n0 + row) * ldk + kt * 16 + c4;
                    cpa16(sBa + (uint32_t)((s * BSZ + half * BN * SPAD + row * SPAD + c4) * 4), src, true);
                }
                asm volatile("cp.async.commit_group;");
            };

            stage_load(0, 0);
            for (int kt = 0; kt < ksteps; kt++) {
                if (kt + 1 < ksteps) {
                    stage_load(kt + 1, (kt + 1) & 1);
                    asm volatile("cp.async.wait_group 1;");
                } else {
                    asm volatile("cp.async.wait_group 0;");
                }
                __syncthreads();
                const int so_a = (kt & 1) * ASZ, so_b = (kt & 1) * BSZ;
                #pragma unroll
                for (int ch = 0; ch < 2; ch++) {
                    uint32_t ah[MFRAG][4], al[MFRAG][4];
                    #pragma unroll
                    for (int mf = 0; mf < MFRAG; mf++) {
                        int arow = (wm * MFRAG + mf) * 16 + (lane & 7) + ((lane >> 3) & 1) * 8;
                        int acol = ch * 8 + (lane >> 4) * 4;
                        uint32_t ad = sAa + (uint32_t)((so_a + arow * SPAD + acol) * 4);
                        ldm4(ah[mf], ad);
                        ldm4(al[mf], ad + (uint32_t)(BM * SPAD * 4));
                    }
                    #pragma unroll
                    for (int ns = 0; ns < 4; ns++) {
                        int l16 = lane & 15;
                        int brow = wn * 32 + ns * 8 + (l16 & 7);
                        int bcol = ch * 8 + ((l16 >> 3) & 1) * 4;
                        uint32_t bd = sBa + (uint32_t)((so_b + brow * SPAD + bcol) * 4);
                        uint32_t bh0, bh1, bl0, bl1;
                        ldm2(bh0, bh1, bd);
                        ldm2(bl0, bl1, bd + (uint32_t)(BN * SPAD * 4));
                        #pragma unroll
                        for (int mf = 0; mf < MFRAG; mf++) {
                            mma_bf16(acc[mf][ns], ah[mf], bh0, bh1);
                            mma_bf16(acc[mf][ns], ah[mf], bl0, bl1);
                            mma_bf16(acc[mf][ns], al[mf], bh0, bh1);
                        }
                    }
                }
                __syncthreads();
            }
        }

        // ---- epilogue ----
        const int rowb = m0 + wm * MFRAG * 16 + (lane >> 2);
        const int colb = n0 + wn * 32 + 2 * (lane & 3);
        #pragma unroll
        for (int mf = 0; mf < MFRAG; mf++) {
            #pragma unroll
            for (int ns = 0; ns < 4; ns++) {
                #pragma unroll
                for (int k = 0; k < 4; k++) {
                    int r = rowb + mf * 16 + ((k >> 1) ? 8 : 0);
                    int n = colb + ns * 8 + (k & 1);
                    if (GROUPED && r >= Mg) continue;
                    float val = acc[mf][ns][k];
                    if (EPI == 0) {
                        OutF[(size_t)r * Ndim + n] = val + bias[n];
                    } else if (EPI == 1) {
                        float v = tanhf(val + bias[n]);
                        splitst(g_sth_h, g_sth_l, (size_t)r * Dm + n, v);
                    } else if (EPI == 2) {
                        float sg = 1.f / (1.f + expf(-(val + bias[n])));
                        float z = g_zf32[(size_t)g_pos[r] * Dm + n];
                        float hn = Hin[(size_t)r * Dm + n] + g_gamma[r] * sg * z;
                        OutF[(size_t)r * Dm + n] = hn;
                        splitst(g_hn_h, g_hn_l, (size_t)r * Dm + n, hn);
                    } else if (EPI == 3) {
                        g_c[(size_t)(gs + r) * Dm + n] = val;
                    } else {   // EPI == 4: DEQ step
                        size_t gi = (size_t)(gs + r) * Dm + n;
                        float v = tanhf(val + g_c[gi]);
                        float zp = ZEROA ? 0.f : g_zf32[gi];
                        float d = v - zp;
                        nsum += d * d;
                        g_zf32[gi] = v;
                        size_t zo = (size_t)(iter & 1) * Bsz * Dm + gi;
                        __nv_bfloat16 hh = __float2bfloat16(v);
                        g_zh[zo] = hh;
                        g_zl[zo] = __float2bfloat16(v - __bfloat162float(hh));
                    }
                }
            }
        }
    }

    if (EPI == 4) {
        // block-wide sum of nsum (NT threads), then last-block finisher
        float v = nsum;
        #pragma unroll
        for (int o = 16; o; o >>= 1) v += __shfl_xor_sync(0xffffffffu, v, o);
        __shared__ float wsum[NT / 32];
        if (lane == 0) wsum[w] = v;
        __syncthreads();
        if (tid == 0) {
            float tot = 0.f;
            #pragma unroll
            for (int i = 0; i < NT / 32; i++) tot += wsum[i];
            atomicAdd(&g_normsq[iter], tot);
            __threadfence();
            int total = gridDim.x * gridDim.y * gridDim.z;
            if (atomicAdd(&g_cnt, 1) == total - 1) {
                g_cnt = 0;
                if (g_normsq[iter] < 1e-5f) g_done = 1;
                __threadfence();
            }
        }
    }
}

// ---------------- host ----------------
extern "C" void kernel_launch(void* const* d_in, const int* in_sizes, int n_in,
                              void* d_out, int out_size)
{
    const float* h      = (const float*)d_in[0];
    const float* fs     = (const float*)d_in[1];
    const float* fe     = (const float*)d_in[2];
    const int*   tok    = (const int*)  d_in[3];
    const float* opemb  = (const float*)d_in[4];
    const float* numw   = (const float*)d_in[5];
    const float* numb   = (const float*)d_in[6];
    const float* addr   = (const float*)d_in[7];
    const float* W      = (const float*)d_in[8];
    const float* U      = (const float*)d_in[9];
    const float* V      = (const float*)d_in[10];
    const float* fsw    = (const float*)d_in[11];
    const float* fsb    = (const float*)d_in[12];
    const float* few    = (const float*)d_in[13];
    const float* feb    = (const float*)d_in[14];
    const float* s1w    = (const float*)d_in[15];
    const float* s1b    = (const float*)d_in[16];
    const float* s2w    = (const float*)d_in[17];
    const float* s2b    = (const float*)d_in[18];
    const float* c1w    = (const float*)d_in[19];
    const float* c1b    = (const float*)d_in[20];
    const float* c2w    = (const float*)d_in[21];
    const float* c2b    = (const float*)d_in[22];
    const float* decw   = (const float*)d_in[23];
    const float* decb   = (const float*)d_in[24];

    float* out        = (float*)d_out;
    float* out_h      = out;
    float* out_logits = out + (size_t)Bsz * Dm;
    float* out_pi     = out + (size_t)Bsz * Dm + (size_t)Bsz * VOCN;

    // ---- weight conversion ----
    k_cvt<0><<<(VOCN * Dm / 4 + 255) / 256, 256>>>((const float4*)decw, VOCN * Dm / 4);
    k_cvt<1><<<(Dm * 2048 / 4 + 255) / 256, 256>>>((const float4*)s1w, Dm * 2048 / 4);
    k_cvt<2><<<(Dm * Dm / 4 + 255) / 256, 256>>>((const float4*)s2w, Dm * Dm / 4);
    dim3 tg(32, 32, Kg), tb(32, 8);
    k_cvtT<0><<<tg, tb>>>(W);
    k_cvtT<1><<<tg, tb>>>(U);
    k_cvtT<2><<<tg, tb>>>(V);

    // ---- routing / embeddings ----
    k_setup<<<Bsz, 256>>>(h, fs, fe, tok, opemb, numw, numb, addr,
                          fsw, fsb, few, feb, c1w, c1b, c2w, c2b, out_pi);
    k_group<<<1, 256>>>();

    // ---- c = [h, f_emb] @ [U;V]^T  (grouped, gathered, K=2048) ----
    k_mma<2, 2, 2, 1, 1, 3, false, false, true>
        <<<dim3(16, 4, Kg), 128>>>(nullptr, nullptr, nullptr, 0, Dm, 2048);

    // ---- DEQ fixed point: iter 1 (z=tanh(c)), iters 2..40 early-exit ----
    k_mma<2, 2, 2, 2, 0, 4, true, false, true>
        <<<dim3(16, 4, Kg), 128>>>(nullptr, nullptr, nullptr, 1, Dm, Dm);
    for (int i = 2; i <= 40; i++) {
        k_mma<2, 2, 2, 2, 0, 4, false, true, true>
            <<<dim3(16, 4, Kg), 128>>>(nullptr, nullptr, nullptr, i, Dm, Dm);
    }

    // ---- stab_h = tanh([h,f] @ s1^T + b1) ----
    k_mma<2, 2, 2, 0, 2, 1, false, false, false>
        <<<dim3(16, 4), 128>>>(s1b, nullptr, nullptr, 0, Dm, 2048);
    // ---- h_next = h + gamma * sigmoid(stab_h @ s2^T + b2) * z_star ----
    k_mma<2, 2, 2, 3, 3, 2, false, false, false>
        <<<dim3(16, 4), 128>>>(s2b, out_h, h, 0, Dm, Dm);
    // ---- logits = h_next @ dec^T + decb ----
    k_mma<2, 2, 2, 4, 4, 0, false, false, false>
        <<<dim3(VOCN / 64, 4), 128>>>(decb, out_logits, nullptr, 0, VOCN, Dm);
}